// round 14
// baseline (speedup 1.0000x reference)
#include <cuda_runtime.h>
#include <math.h>

// Problem constants (fixed by setup_inputs)
#define BS    16
#define T     1024
#define DF    80
#define DF4   20
#define SIZE  4096
#define TPB   128        // quad per row -> 32 rows per block
#define RPB   32
#define GPB   4          // 8-row groups per block
#define NZ    16         // split factor for WIDE groups
#define THRESH 96
#define GRPS  (SIZE / 8) // 512
#define TPAD  8
#define PT    (T + TPAD)
#define NROW  (BS * SIZE)
#define WK    160        // k-tile for the weight phase
#define WST   165        // w_sm row stride (odd -> conflict-free banks)
#define FULLM 0xFFFFFFFFu

// Device scratch (allocation-free)
__device__ float g_cs[BS * PT];            // sorted centers (+INF pad)
__device__ int   g_ci[BS * PT];            // permutation   (0 pad)
__device__ __align__(16) float g_hp[BS * PT * DF];        // permuted h (0 pad)
__device__ int2  g_win[BS * GRPS];         // per 8-row group: union {wlo,whi}
__device__ float g_smax[NROW];             // per row: exact max score
__device__ __align__(16) float g_part[(size_t)NZ * NROW * DF];
__device__ float g_lpart[NZ * NROW];

// packed fp32x2 helpers (sm_100+): two independent IEEE fp32 ops per instr
__device__ __forceinline__ void ffma2(unsigned long long& d,
                                      unsigned long long a,
                                      unsigned long long b) {
    asm("fma.rn.f32x2 %0, %1, %2, %0;" : "+l"(d) : "l"(a), "l"(b));
}
__device__ __forceinline__ unsigned long long pack2(float x) {
    unsigned long long r;
    asm("mov.b64 %0, {%1, %1};" : "=l"(r) : "f"(x));
    return r;
}
__device__ __forceinline__ float lo32(unsigned long long u) {
    return __uint_as_float((unsigned)(u & 0xFFFFFFFFull));
}
__device__ __forceinline__ float hi32(unsigned long long u) {
    return __uint_as_float((unsigned)(u >> 32));
}

// ---------------------------------------------------------------------------
// Kernel 1: prep (validated R13).
// b==0: c = d/2 (reference zeroes the row) -> hybrid bitonic sort.
// b>0 : assoc-scan-tree fp32 cumsum; sorted order is a rotation.
// ---------------------------------------------------------------------------
__global__ void prep_kernel(const float* __restrict__ d) {
    __shared__ float r[2047];
    __shared__ float sarr[2047];
    __shared__ float sv[T];
    __shared__ int   si[T];
    const int b = blockIdx.x;
    const int t = threadIdx.x;
    const float v = d[b * T + t];

    if (b == 0) {
        float key = 0.5f * v;
        int   idx = t;
        for (int k = 2; k <= T; k <<= 1) {
            for (int j = k >> 1; j >= 32; j >>= 1) {     // cross-warp: smem
                sv[t] = key; si[t] = idx;
                __syncthreads();
                int p = t ^ j;
                float pv = sv[p]; int pi = si[p];
                bool keepmin = (((t & k) == 0) == ((t & j) == 0));
                bool take = keepmin ? (pv < key) : (pv > key);
                if (take) { key = pv; idx = pi; }
                __syncthreads();
            }
            const int j0 = (k >> 1) < 16 ? (k >> 1) : 16;
            for (int j = j0; j >= 1; j >>= 1) {          // in-warp: shfl
                float pv = __shfl_xor_sync(FULLM, key, j);
                int   pi = __shfl_xor_sync(FULLM, idx, j);
                bool keepmin = (((t & k) == 0) == ((t & j) == 0));
                bool take = keepmin ? (pv < key) : (pv > key);
                if (take) { key = pv; idx = pi; }
            }
        }
        g_cs[t] = key;
        g_ci[t] = idx;
    } else {
        r[t] = v;
        __syncthreads();
        {   // upsweep
            int off = 0, n = T;
            while (n > 1) {
                int noff = off + n;
                if (t < (n >> 1))
                    r[noff + t] = __fadd_rn(r[off + 2 * t], r[off + 2 * t + 1]);
                __syncthreads();
                off = noff; n >>= 1;
            }
        }
        if (t == 0) sarr[2046] = r[2046];
        __syncthreads();
        #pragma unroll
        for (int L = 9; L >= 0; --L) {   // downsweep
            const int n    = T >> L;
            const int off  = 2048 - (2048 >> L);
            const int offn = 2048 - (2048 >> (L + 1));
            if (t < n) {
                float val;
                if (t == 0)     val = r[off];
                else if (t & 1) val = sarr[offn + (t >> 1)];
                else            val = __fadd_rn(sarr[offn + (t >> 1) - 1], r[off + t]);
                sarr[off + t] = val;
            }
            __syncthreads();
        }
        float cs = (t == 0) ? sarr[T - 1] : sarr[t - 1];
        float cv = __fadd_rn(0.5f * v, cs);
        int dest = (t == 0) ? (T - 1) : (t - 1);     // sorted = rotation
        g_cs[b * PT + dest] = cv;
        g_ci[b * PT + dest] = t;
    }
    if (t < TPAD) { g_cs[b * PT + T + t] = INFINITY; g_ci[b * PT + T + t] = 0; }
}

// ---------------------------------------------------------------------------
// Kernel 1b: h_perm[b][k][:] = h[b][ci[b][k]][:]; pad rows zeroed.
// ---------------------------------------------------------------------------
__global__ void perm_kernel(const float* __restrict__ h) {
    const int e = blockIdx.x * blockDim.x + threadIdx.x;
    const int c = e % DF;
    const int k = (e / DF) % PT;
    const int b = e / (DF * PT);
    if (b >= BS) return;
    float v = 0.0f;
    if (k < T) {
        int src = g_ci[b * PT + k];
        v = h[((size_t)b * T + src) * DF + c];
    }
    g_hp[((size_t)b * PT + k) * DF + c] = v;
}

// ---------------------------------------------------------------------------
// Kernel 1c: per-row score_max + per-8-row-group union window table.
// ---------------------------------------------------------------------------
__global__ void __launch_bounds__(256) win_kernel(const float* __restrict__ sigma) {
    __shared__ float c_sh[T];
    const int b = blockIdx.y;
    const int tid = threadIdx.x;
    const int s = blockIdx.x * 256 + tid;

    for (int i = tid; i < T; i += 256)
        c_sh[i] = g_cs[b * PT + i];
    __syncthreads();

    const float sg     = sigma[0];
    const float two_s2 = 2.0f * sg * sg;
    const float tval   = (float)s + 1.5f;

    auto lower = [&](float x) -> int {
        int lo = 0, hi = T;
        while (lo < hi) {
            int m = (lo + hi) >> 1;
            if (c_sh[m] > x) hi = m; else lo = m + 1;
        }
        return lo;
    };

    int kc = lower(tval);
    int kA = kc < (T - 1) ? kc : (T - 1);
    int kB = (kc - 1) > 0 ? (kc - 1) : 0;
    float dA  = __fsub_rn(tval, c_sh[kA]);
    float dB  = __fsub_rn(tval, c_sh[kB]);
    float sqA = __fmul_rn(dA, dA);
    float sqB = __fmul_rn(dB, dB);
    float sqmin = fminf(sqA, sqB);
    const float score_max = -__fdiv_rn(sqmin, two_s2);
    const float rr = sqrtf(sqmin + 24.0f * two_s2);
    int klo = lower(tval - rr);
    int khi = lower(tval + rr) - 1;

    g_smax[(size_t)b * SIZE + s] = score_max;

    #pragma unroll
    for (int o = 1; o < 8; o <<= 1) {
        klo = min(klo, __shfl_xor_sync(FULLM, klo, o));
        khi = max(khi, __shfl_xor_sync(FULLM, khi, o));
    }
    if ((tid & 7) == 0)
        g_win[b * GRPS + (s >> 3)] = make_int2(klo, khi);
}

// ---------------------------------------------------------------------------
// Main kernel: per k-tile, PHASE 1 computes all 32xWK quantization-faithful
// weights into smem (independent exps, per-warp-segment guarded; slots past
// the tile end zeroed so tiles partition exactly). PHASE 2 is a pure
// LDS + LDG + packed-FFMA2 stream with no exp/shfl/div in the chain.
//   dt=fsub; sq=fmul; sc=-fdiv(sq,2s^2) [POW2: fmul by exact recip == fdiv];
//   e=fsub(sc,smax); w=expf(e)
// ---------------------------------------------------------------------------
__global__ void __launch_bounds__(TPB, 8) alignment_kernel(
    const float* __restrict__ sigma, float* __restrict__ out)
{
    __shared__ float w_sm[RPB * WST];     // 21120 B
    __shared__ float s_smax[RPB];
    __shared__ int   s_alo[GPB], s_ahi[GPB];
    __shared__ int   s_klo, s_khi;

    const int b   = blockIdx.y;
    const int z   = blockIdx.z;
    const int bx  = blockIdx.x;
    const int tid = threadIdx.x;
    const int f   = tid & 3;
    const int row = tid >> 2;              // 0..31
    const int wrp = tid >> 5;              // 0..3
    const int s   = bx * RPB + row;

    const int2 wv = g_win[b * GRPS + bx * GPB + wrp];
    const int wlo = wv.x, whi = wv.y, len = whi - wlo + 1;
    const bool narrow = (len <= THRESH);
    bool active; int alo, ahi;
    if (narrow) { active = (z == 0); alo = wlo; ahi = whi; }
    else        { active = true;
                  alo = wlo + (len * z) / NZ;
                  ahi = wlo + (len * (z + 1)) / NZ - 1; }

    if (tid == 0) { s_klo = 0x7FFFFFFF; s_khi = -1; }
    __syncthreads();
    if ((tid & 31) == 0) {
        if (active) { atomicMin(&s_klo, alo); atomicMax(&s_khi, ahi); }
        s_alo[wrp] = active ? alo : 1;
        s_ahi[wrp] = active ? ahi : 0;
    }
    if (tid < RPB) s_smax[tid] = g_smax[(size_t)b * SIZE + bx * RPB + tid];
    __syncthreads();
    if (s_khi < 0) return;                 // whole block inactive (uniform)
    if (!active) { alo = 1; ahi = 0; }     // empty range, stay for barriers

    const int kbase = s_klo;
    const int kcnt  = s_khi + 1 - kbase;

    const float sg     = sigma[0];
    const float two_s2 = 2.0f * sg * sg;
    const unsigned tb  = __float_as_uint(two_s2);
    const bool pow2    = ((tb & 0x007FFFFFu) == 0u) && (two_s2 > 0.0f);
    const float inv2s2 = 1.0f / two_s2;    // exact reciprocal when pow2
    const float* cb    = g_cs + b * PT;
    const float4* __restrict__ hpb = (const float4*)g_hp + (size_t)b * PT * DF4;

    // phase-1 thread identity: row r1 = lane, k-substride j1
    const int   r1    = tid & 31;
    const int   j1    = tid >> 5;
    const float tval1 = (float)(bx * RPB + r1) + 1.5f;
    const float smax1 = s_smax[r1];
    const int   alo1  = s_alo[r1 >> 3];
    const int   ahi1  = s_ahi[r1 >> 3];

    float l = 0.0f;
    unsigned long long acc2[10];
    #pragma unroll
    for (int j = 0; j < 10; ++j) acc2[j] = 0ull;

    for (int kt = kbase; kt < kbase + kcnt; kt += WK) {
        const int tcnt = min(WK, kbase + kcnt - kt);

        // ---- phase 1: weights (independent exps; banks conflict-free)
        if (pow2) {
            for (int jj = j1; jj < tcnt + 3; jj += 4) {
                const int k = kt + jj;
                float cc = __ldg(cb + k);
                float dt = __fsub_rn(tval1, cc);
                float sq = __fmul_rn(dt, dt);
                float sc = -__fmul_rn(sq, inv2s2);
                float e  = __fsub_rn(sc, smax1);
                float w  = __expf(e);
                if (k < alo1 || k > ahi1 || jj >= tcnt) w = 0.0f;
                w_sm[r1 * WST + jj] = w;
            }
        } else {
            for (int jj = j1; jj < tcnt + 3; jj += 4) {
                const int k = kt + jj;
                float cc = __ldg(cb + k);
                float dt = __fsub_rn(tval1, cc);
                float sq = __fmul_rn(dt, dt);
                float sc = -__fdiv_rn(sq, two_s2);
                float e  = __fsub_rn(sc, smax1);
                float w  = __expf(e);
                if (k < alo1 || k > ahi1 || jj >= tcnt) w = 0.0f;
                w_sm[r1 * WST + jj] = w;
            }
        }
        __syncthreads();

        // ---- phase 2: pure load + packed-FMA stream
        const int plo = max(alo, kt);
        const int phi = min(ahi, kt + tcnt - 1);
        const float* wr = w_sm + row * WST;
        for (int k0 = plo; k0 <= phi; k0 += 4) {
            const int o = k0 - kt;
            float w0 = wr[o];
            float w1 = wr[o + 1];
            float w2 = wr[o + 2];
            float w3 = wr[o + 3];
            l += ((w0 + w1) + (w2 + w3));
            unsigned long long p0 = pack2(w0), p1 = pack2(w1);
            unsigned long long p2 = pack2(w2), p3 = pack2(w3);
            const ulonglong2* h0 = (const ulonglong2*)(hpb + (size_t)(k0    ) * DF4 + f);
            const ulonglong2* h1 = (const ulonglong2*)(hpb + (size_t)(k0 + 1) * DF4 + f);
            const ulonglong2* h2 = (const ulonglong2*)(hpb + (size_t)(k0 + 2) * DF4 + f);
            const ulonglong2* h3 = (const ulonglong2*)(hpb + (size_t)(k0 + 3) * DF4 + f);
            #pragma unroll
            for (int j = 0; j < 5; ++j) {
                ulonglong2 v0 = h0[4 * j];
                ffma2(acc2[2 * j], v0.x, p0); ffma2(acc2[2 * j + 1], v0.y, p0);
                ulonglong2 v1 = h1[4 * j];
                ffma2(acc2[2 * j], v1.x, p1); ffma2(acc2[2 * j + 1], v1.y, p1);
                ulonglong2 v2 = h2[4 * j];
                ffma2(acc2[2 * j], v2.x, p2); ffma2(acc2[2 * j + 1], v2.y, p2);
                ulonglong2 v3 = h3[4 * j];
                ffma2(acc2[2 * j], v3.x, p3); ffma2(acc2[2 * j + 1], v3.y, p3);
            }
        }
        __syncthreads();   // before next tile overwrites w_sm
    }

    if (!active) return;

    if (narrow) {
        const float linv = 1.0f / l;
        float4* o = (float4*)out + ((size_t)b * SIZE + s) * DF4 + f;
        #pragma unroll
        for (int j = 0; j < 5; ++j) {
            float4 v;
            v.x = lo32(acc2[2 * j])     * linv;
            v.y = hi32(acc2[2 * j])     * linv;
            v.z = lo32(acc2[2 * j + 1]) * linv;
            v.w = hi32(acc2[2 * j + 1]) * linv;
            o[4 * j] = v;
        }
    } else {
        const size_t rowid = (size_t)b * SIZE + s;
        float4* po = (float4*)g_part + ((size_t)z * NROW + rowid) * DF4 + f;
        #pragma unroll
        for (int j = 0; j < 5; ++j) {
            float4 v;
            v.x = lo32(acc2[2 * j]);
            v.y = hi32(acc2[2 * j]);
            v.z = lo32(acc2[2 * j + 1]);
            v.w = hi32(acc2[2 * j + 1]);
            po[4 * j] = v;
        }
        if (f == 0) g_lpart[(size_t)z * NROW + rowid] = l;
    }
}

// ---------------------------------------------------------------------------
// Kernel 3: combine — only WIDE rows (narrow written directly by main).
// ---------------------------------------------------------------------------
__global__ void combine_kernel(float* __restrict__ out) {
    const int e = blockIdx.x * blockDim.x + threadIdx.x;  // float4 id
    if (e >= NROW * DF4) return;
    const int rowid = e / DF4;
    const int b = rowid / SIZE;
    const int s = rowid % SIZE;

    int2 wv = g_win[b * GRPS + (s >> 3)];
    if (wv.y - wv.x + 1 <= THRESH) return;

    float lsum = 0.0f;
    #pragma unroll
    for (int z = 0; z < NZ; ++z)
        lsum += g_lpart[(size_t)z * NROW + rowid];

    float4 v = make_float4(0.f, 0.f, 0.f, 0.f);
    #pragma unroll
    for (int z = 0; z < NZ; ++z) {
        float4 p = ((const float4*)g_part)[(size_t)z * NROW * DF4 + e];
        v.x += p.x; v.y += p.y; v.z += p.z; v.w += p.w;
    }
    const float linv = 1.0f / lsum;
    v.x *= linv; v.y *= linv; v.z *= linv; v.w *= linv;
    ((float4*)out)[e] = v;
}

// ---------------------------------------------------------------------------
extern "C" void kernel_launch(void* const* d_in, const int* in_sizes, int n_in,
                              void* d_out, int out_size) {
    const float* h     = (const float*)d_in[0];  // [16,1024,80]
    const float* d     = (const float*)d_in[1];  // [16,1024]
    const float* sigma = (const float*)d_in[2];  // [1]

    prep_kernel<<<BS, T>>>(d);
    const int pelems = BS * PT * DF;
    perm_kernel<<<(pelems + 255) / 256, 256>>>(h);

    dim3 wgrid(SIZE / 256, BS);
    win_kernel<<<wgrid, 256>>>(sigma);

    dim3 mgrid(SIZE / RPB, BS, NZ);              // 128 x 16 x 16
    alignment_kernel<<<mgrid, TPB>>>(sigma, (float*)d_out);

    const int celems = NROW * DF4;
    combine_kernel<<<(celems + 255) / 256, 256>>>((float*)d_out);
}

// round 15
// speedup vs baseline: 1.2450x; 1.2450x over previous
#include <cuda_runtime.h>
#include <math.h>

// Problem constants (fixed by setup_inputs)
#define BS    16
#define T     1024
#define DF    80
#define DF4   20
#define SIZE  4096
#define TPB   128        // quad per row -> 32 rows per block
#define RPB   32
#define GPB   4          // 8-row groups per block
#define NZ    16         // split factor for WIDE groups
#define THRESH 96
#define GRPS  (SIZE / 8) // 512
#define TPAD  8
#define PT    (T + TPAD)
#define NROW  (BS * SIZE)
#define KMAX  150        // h-tile rows staged in smem (150*320B = 48000B)
#define WGRID 256        // wide kernel blocks (x4 warps = 1024 work slots)
#define FULLM 0xFFFFFFFFu

// Device scratch (allocation-free)
__device__ float g_cs[BS * PT];            // sorted centers (+INF pad)
__device__ int   g_ci[BS * PT];            // permutation   (0 pad)
__device__ __align__(16) float g_hp[BS * PT * DF];   // permuted h (0 pad)
__device__ int2  g_win[BS * GRPS];         // per 8-row group: union {wlo,whi}
__device__ float g_smax[NROW];             // per row: exact max score
__device__ __align__(16) float g_part[(size_t)NZ * NROW * DF];
__device__ float g_lpart[NZ * NROW];
__device__ int   g_q[BS * GRPS];           // queue of WIDE group ids
__device__ int   g_qn;                     // queue length

// ---------------------------------------------------------------------------
// Kernel 1: prep (validated R13).
// b==0: c = d/2 (reference zeroes the row) -> hybrid bitonic sort.
// b>0 : assoc-scan-tree fp32 cumsum (reference association); sorted order is
//       a rotation (cv[1..1023] ascending, cv[0] is the max).
// Also resets the wide queue counter.
// ---------------------------------------------------------------------------
__global__ void prep_kernel(const float* __restrict__ d) {
    __shared__ float r[2047];
    __shared__ float sarr[2047];
    __shared__ float sv[T];
    __shared__ int   si[T];
    const int b = blockIdx.x;
    const int t = threadIdx.x;
    const float v = d[b * T + t];

    if (b == 0 && t == 0) g_qn = 0;

    if (b == 0) {
        float key = 0.5f * v;
        int   idx = t;
        for (int k = 2; k <= T; k <<= 1) {
            for (int j = k >> 1; j >= 32; j >>= 1) {     // cross-warp: smem
                sv[t] = key; si[t] = idx;
                __syncthreads();
                int p = t ^ j;
                float pv = sv[p]; int pi = si[p];
                bool keepmin = (((t & k) == 0) == ((t & j) == 0));
                bool take = keepmin ? (pv < key) : (pv > key);
                if (take) { key = pv; idx = pi; }
                __syncthreads();
            }
            const int j0 = (k >> 1) < 16 ? (k >> 1) : 16;
            for (int j = j0; j >= 1; j >>= 1) {          // in-warp: shfl
                float pv = __shfl_xor_sync(FULLM, key, j);
                int   pi = __shfl_xor_sync(FULLM, idx, j);
                bool keepmin = (((t & k) == 0) == ((t & j) == 0));
                bool take = keepmin ? (pv < key) : (pv > key);
                if (take) { key = pv; idx = pi; }
            }
        }
        g_cs[t] = key;
        g_ci[t] = idx;
    } else {
        r[t] = v;
        __syncthreads();
        {   // upsweep
            int off = 0, n = T;
            while (n > 1) {
                int noff = off + n;
                if (t < (n >> 1))
                    r[noff + t] = __fadd_rn(r[off + 2 * t], r[off + 2 * t + 1]);
                __syncthreads();
                off = noff; n >>= 1;
            }
        }
        if (t == 0) sarr[2046] = r[2046];
        __syncthreads();
        #pragma unroll
        for (int L = 9; L >= 0; --L) {   // downsweep
            const int n    = T >> L;
            const int off  = 2048 - (2048 >> L);
            const int offn = 2048 - (2048 >> (L + 1));
            if (t < n) {
                float val;
                if (t == 0)     val = r[off];
                else if (t & 1) val = sarr[offn + (t >> 1)];
                else            val = __fadd_rn(sarr[offn + (t >> 1) - 1], r[off + t]);
                sarr[off + t] = val;
            }
            __syncthreads();
        }
        float cs = (t == 0) ? sarr[T - 1] : sarr[t - 1];
        float cv = __fadd_rn(0.5f * v, cs);
        int dest = (t == 0) ? (T - 1) : (t - 1);     // sorted = rotation
        g_cs[b * PT + dest] = cv;
        g_ci[b * PT + dest] = t;
    }
    if (t < TPAD) { g_cs[b * PT + T + t] = INFINITY; g_ci[b * PT + T + t] = 0; }
}

// ---------------------------------------------------------------------------
// Kernel 1b: h_perm[b][k][:] = h[b][ci[b][k]][:]; pad rows zeroed.
// ---------------------------------------------------------------------------
__global__ void perm_kernel(const float* __restrict__ h) {
    const int e = blockIdx.x * blockDim.x + threadIdx.x;
    const int c = e % DF;
    const int k = (e / DF) % PT;
    const int b = e / (DF * PT);
    if (b >= BS) return;
    float v = 0.0f;
    if (k < T) {
        int src = g_ci[b * PT + k];
        v = h[((size_t)b * T + src) * DF + c];
    }
    g_hp[((size_t)b * PT + k) * DF + c] = v;
}

// ---------------------------------------------------------------------------
// Kernel 1c: per-row score_max + per-group union windows + WIDE queue.
// ---------------------------------------------------------------------------
__global__ void __launch_bounds__(256) win_kernel(const float* __restrict__ sigma) {
    __shared__ float c_sh[T];
    const int b = blockIdx.y;
    const int tid = threadIdx.x;
    const int s = blockIdx.x * 256 + tid;

    for (int i = tid; i < T; i += 256)
        c_sh[i] = g_cs[b * PT + i];
    __syncthreads();

    const float sg     = sigma[0];
    const float two_s2 = 2.0f * sg * sg;
    const float tval   = (float)s + 1.5f;

    auto lower = [&](float x) -> int {
        int lo = 0, hi = T;
        while (lo < hi) {
            int m = (lo + hi) >> 1;
            if (c_sh[m] > x) hi = m; else lo = m + 1;
        }
        return lo;
    };

    int kc = lower(tval);
    int kA = kc < (T - 1) ? kc : (T - 1);
    int kB = (kc - 1) > 0 ? (kc - 1) : 0;
    float dA  = __fsub_rn(tval, c_sh[kA]);
    float dB  = __fsub_rn(tval, c_sh[kB]);
    float sqA = __fmul_rn(dA, dA);
    float sqB = __fmul_rn(dB, dB);
    float sqmin = fminf(sqA, sqB);
    const float score_max = -__fdiv_rn(sqmin, two_s2);
    const float rr = sqrtf(sqmin + 24.0f * two_s2);
    int klo = lower(tval - rr);
    int khi = lower(tval + rr) - 1;

    g_smax[(size_t)b * SIZE + s] = score_max;

    #pragma unroll
    for (int o = 1; o < 8; o <<= 1) {
        klo = min(klo, __shfl_xor_sync(FULLM, klo, o));
        khi = max(khi, __shfl_xor_sync(FULLM, khi, o));
    }
    if ((tid & 7) == 0) {
        const int gidx = b * GRPS + (s >> 3);
        g_win[gidx] = make_int2(klo, khi);
        if (khi - klo + 1 > THRESH) {
            int p = atomicAdd(&g_qn, 1);
            g_q[p] = gidx;
        }
    }
}

// ---------------------------------------------------------------------------
// Shared inner body (validated R13): chunk-of-4 quad loop.
//   dt=fsub; sq=fmul; sc=-fdiv(sq,2s^2) [POW2: fmul by exact recip == fdiv];
//   e=fsub(sc,smax); w=expf(e). Guard kk>ahi gives exact segment partition.
// USM: h and c from block smem tile; else global (L2).
// ---------------------------------------------------------------------------
template<bool POW2, bool USM>
__device__ __forceinline__ float body(
    const float* __restrict__ cb,            // g_cs + b*PT (global)
    const float* __restrict__ csm,           // staged c (smem), base kbase
    const float4* __restrict__ hpb,          // global h_perm batch base
    const float4* __restrict__ hsm, int kbase,
    int alo, int ahi, int f, float tval, float smax,
    float two_s2, float inv2s2, float4* acc)
{
    float l = 0.0f;
    for (int k0 = alo; k0 <= ahi; k0 += 4) {
        const int kk = k0 + f;
        float cc = USM ? csm[kk - kbase] : __ldg(cb + kk);
        float dt = __fsub_rn(tval, cc);
        float sq = __fmul_rn(dt, dt);
        float sc = POW2 ? -__fmul_rn(sq, inv2s2) : -__fdiv_rn(sq, two_s2);
        float e  = __fsub_rn(sc, smax);
        float w0 = __expf(e);
        if (kk > ahi) w0 = 0.0f;
        float w1 = __shfl_xor_sync(FULLM, w0, 1);
        float w2 = __shfl_xor_sync(FULLM, w0, 2);
        float w3 = __shfl_xor_sync(FULLM, w1, 2);
        l += ((w0 + w1) + (w2 + w3));

        const int r0 = k0 + f, r1 = k0 + (f ^ 1), r2 = k0 + (f ^ 2), r3 = k0 + (f ^ 3);
        #pragma unroll
        for (int j = 0; j < 5; ++j) {
            const int col = f + 4 * j;
            float4 v0 = USM ? hsm[(r0 - kbase) * DF4 + col] : hpb[(size_t)r0 * DF4 + col];
            acc[j].x += w0 * v0.x; acc[j].y += w0 * v0.y;
            acc[j].z += w0 * v0.z; acc[j].w += w0 * v0.w;
            float4 v1 = USM ? hsm[(r1 - kbase) * DF4 + col] : hpb[(size_t)r1 * DF4 + col];
            acc[j].x += w1 * v1.x; acc[j].y += w1 * v1.y;
            acc[j].z += w1 * v1.z; acc[j].w += w1 * v1.w;
            float4 v2 = USM ? hsm[(r2 - kbase) * DF4 + col] : hpb[(size_t)r2 * DF4 + col];
            acc[j].x += w2 * v2.x; acc[j].y += w2 * v2.y;
            acc[j].z += w2 * v2.z; acc[j].w += w2 * v2.w;
            float4 v3 = USM ? hsm[(r3 - kbase) * DF4 + col] : hpb[(size_t)r3 * DF4 + col];
            acc[j].x += w3 * v3.x; acc[j].y += w3 * v3.y;
            acc[j].z += w3 * v3.z; acc[j].w += w3 * v3.w;
        }
    }
    return l;
}

// ---------------------------------------------------------------------------
// Kernel 2a: NARROW groups only. Grid 128x16 — no ghost blocks. Full window,
// direct normalized output. Block stages h + c union range in smem.
// ---------------------------------------------------------------------------
__global__ void __launch_bounds__(TPB) narrow_kernel(
    const float* __restrict__ sigma, float* __restrict__ out)
{
    __shared__ float4 h_sm[KMAX * DF4];      // 48000 B
    __shared__ float  c_sm[KMAX + 4];
    __shared__ int s_klo, s_khi;
    const int b   = blockIdx.y;
    const int bx  = blockIdx.x;
    const int tid = threadIdx.x;
    const int f   = tid & 3;
    const int row = tid >> 2;                // 0..31
    const int s   = bx * RPB + row;
    const int wrp = tid >> 5;                // 0..3

    const int2 wv = g_win[b * GRPS + bx * GPB + wrp];
    const int wlo = wv.x, whi = wv.y, len = whi - wlo + 1;
    const bool active = (len <= THRESH);
    const int alo = wlo, ahi = whi;

    if (tid == 0) { s_klo = 0x7FFFFFFF; s_khi = -1; }
    __syncthreads();
    if (active && (tid & 31) == 0) { atomicMin(&s_klo, alo); atomicMax(&s_khi, ahi); }
    __syncthreads();
    if (s_khi < 0) return;                   // all 4 groups wide (rare)

    const int kbase  = s_klo;
    const int kcount = s_khi + 4 - kbase;    // loop reads rows up to ahi+3
    const bool usm   = (kcount <= KMAX);
    const float* cb  = g_cs + b * PT;
    const float4* __restrict__ hpb = (const float4*)g_hp + (size_t)b * PT * DF4;

    if (usm) {
        const float4* src = hpb + (size_t)kbase * DF4;
        for (int i = tid; i < kcount * DF4; i += TPB) h_sm[i] = src[i];
        for (int i = tid; i < kcount; i += TPB) c_sm[i] = cb[kbase + i];
    }
    __syncthreads();
    if (!active) return;                     // after all block-wide syncs

    const float sg     = sigma[0];
    const float two_s2 = 2.0f * sg * sg;
    const unsigned tb  = __float_as_uint(two_s2);
    const bool pow2    = ((tb & 0x007FFFFFu) == 0u) && (two_s2 > 0.0f);
    const float inv2s2 = 1.0f / two_s2;      // exact reciprocal when pow2
    const float tval   = (float)s + 1.5f;
    const float smax   = g_smax[(size_t)b * SIZE + s];

    float4 acc[5];
    #pragma unroll
    for (int j = 0; j < 5; ++j) acc[j] = make_float4(0.f, 0.f, 0.f, 0.f);

    float l;
    if (pow2) {
        if (usm) l = body<true , true >(cb, c_sm, hpb, h_sm, kbase, alo, ahi, f, tval, smax, two_s2, inv2s2, acc);
        else     l = body<true , false>(cb, c_sm, hpb, h_sm, kbase, alo, ahi, f, tval, smax, two_s2, inv2s2, acc);
    } else {
        if (usm) l = body<false, true >(cb, c_sm, hpb, h_sm, kbase, alo, ahi, f, tval, smax, two_s2, inv2s2, acc);
        else     l = body<false, false>(cb, c_sm, hpb, h_sm, kbase, alo, ahi, f, tval, smax, two_s2, inv2s2, acc);
    }

    const float linv = 1.0f / l;
    float4* o = (float4*)out + ((size_t)b * SIZE + s) * DF4 + f;
    #pragma unroll
    for (int j = 0; j < 5; ++j) {
        float4 v;
        v.x = acc[j].x * linv; v.y = acc[j].y * linv;
        v.z = acc[j].z * linv; v.w = acc[j].w * linv;
        o[4 * j] = v;
    }
}

// ---------------------------------------------------------------------------
// Kernel 2b: WIDE groups from the queue. One warp per (group, z) item.
// Global-path body; writes partial slabs for combine.
// ---------------------------------------------------------------------------
__global__ void __launch_bounds__(TPB) wide_kernel(
    const float* __restrict__ sigma)
{
    const int tid  = threadIdx.x;
    const int wrp  = tid >> 5;
    const int lane = tid & 31;
    const int f    = lane & 3;
    const int quad = lane >> 2;              // row in group

    const int qn    = g_qn;
    const int total = qn * NZ;

    const float sg     = sigma[0];
    const float two_s2 = 2.0f * sg * sg;
    const unsigned tb  = __float_as_uint(two_s2);
    const bool pow2    = ((tb & 0x007FFFFFu) == 0u) && (two_s2 > 0.0f);
    const float inv2s2 = 1.0f / two_s2;

    for (int item = blockIdx.x * 4 + wrp; item < total; item += WGRID * 4) {
        const int gidx = g_q[item / NZ];
        const int z    = item % NZ;
        const int b    = gidx / GRPS;
        const int grp  = gidx % GRPS;
        const int s    = grp * 8 + quad;

        const int2 wv = g_win[gidx];
        const int wlo = wv.x, len = wv.y - wv.x + 1;
        const int alo = wlo + (len * z) / NZ;
        const int ahi = wlo + (len * (z + 1)) / NZ - 1;

        const float tval = (float)s + 1.5f;
        const float smax = g_smax[(size_t)b * SIZE + s];
        const float* cb  = g_cs + b * PT;
        const float4* __restrict__ hpb =
            (const float4*)g_hp + (size_t)b * PT * DF4;

        float4 acc[5];
        #pragma unroll
        for (int j = 0; j < 5; ++j) acc[j] = make_float4(0.f, 0.f, 0.f, 0.f);

        float l;
        if (pow2) l = body<true , false>(cb, (const float*)0, hpb, (const float4*)0, 0,
                                         alo, ahi, f, tval, smax, two_s2, inv2s2, acc);
        else      l = body<false, false>(cb, (const float*)0, hpb, (const float4*)0, 0,
                                         alo, ahi, f, tval, smax, two_s2, inv2s2, acc);

        const size_t rowid = (size_t)b * SIZE + s;
        float4* po = (float4*)g_part + ((size_t)z * NROW + rowid) * DF4 + f;
        #pragma unroll
        for (int j = 0; j < 5; ++j) po[4 * j] = acc[j];
        if (f == 0) g_lpart[(size_t)z * NROW + rowid] = l;
    }
}

// ---------------------------------------------------------------------------
// Kernel 3: combine — only WIDE rows (narrow written directly).
// ---------------------------------------------------------------------------
__global__ void combine_kernel(float* __restrict__ out) {
    const int e = blockIdx.x * blockDim.x + threadIdx.x;  // float4 id
    if (e >= NROW * DF4) return;
    const int rowid = e / DF4;
    const int b = rowid / SIZE;
    const int s = rowid % SIZE;

    int2 wv = g_win[b * GRPS + (s >> 3)];
    if (wv.y - wv.x + 1 <= THRESH) return;

    float lsum = 0.0f;
    #pragma unroll
    for (int z = 0; z < NZ; ++z)
        lsum += g_lpart[(size_t)z * NROW + rowid];

    float4 v = make_float4(0.f, 0.f, 0.f, 0.f);
    #pragma unroll
    for (int z = 0; z < NZ; ++z) {
        float4 p = ((const float4*)g_part)[(size_t)z * NROW * DF4 + e];
        v.x += p.x; v.y += p.y; v.z += p.z; v.w += p.w;
    }
    const float linv = 1.0f / lsum;
    v.x *= linv; v.y *= linv; v.z *= linv; v.w *= linv;
    ((float4*)out)[e] = v;
}

// ---------------------------------------------------------------------------
extern "C" void kernel_launch(void* const* d_in, const int* in_sizes, int n_in,
                              void* d_out, int out_size) {
    const float* h     = (const float*)d_in[0];  // [16,1024,80]
    const float* d     = (const float*)d_in[1];  // [16,1024]
    const float* sigma = (const float*)d_in[2];  // [1]

    prep_kernel<<<BS, T>>>(d);
    const int pelems = BS * PT * DF;
    perm_kernel<<<(pelems + 255) / 256, 256>>>(h);

    dim3 wgrid(SIZE / 256, BS);
    win_kernel<<<wgrid, 256>>>(sigma);

    dim3 ngrid(SIZE / RPB, BS);                  // 128 x 16, no ghost z
    narrow_kernel<<<ngrid, TPB>>>(sigma, (float*)d_out);
    wide_kernel<<<WGRID, TPB>>>(sigma);

    const int celems = NROW * DF4;
    combine_kernel<<<(celems + 255) / 256, 256>>>((float*)d_out);
}